// round 2
// baseline (speedup 1.0000x reference)
#include <cuda_runtime.h>
#include <math_constants.h>

#define BZ   32
#define RVN  16
#define RVL  64
#define H    256
#define NTOK 1024   // tokens per batch (rv_num*rv_len), same for a and b
#define HID  256
#define EPSF 1e-8f
#define NEGV -100000000.0f

// ---------------- scratch (device globals; no allocation allowed) ----------
__device__ __align__(16) float g_invb[BZ * NTOK];
__device__ __align__(16) float g_sb_part[8][BZ][H];
__device__ __align__(16) float g_sb[BZ * H];
__device__ __align__(16) float g_denom[BZ];
__device__ __align__(16) float g_word[BZ * NTOK];
__device__ __align__(16) float g_inva[BZ * NTOK];
__device__ __align__(16) float g_mean[BZ * NTOK];
__device__ __align__(16) float g_max[BZ * NTOK];
__device__ int g_mask_byte;  // 1 = masks are 1-byte bools, 0 = 4-byte (int32/float32)

__device__ __forceinline__ bool mask_at(const void* m, int i) {
    if (g_mask_byte)
        return ((const unsigned char*)m)[i] != 0;
    return ((const unsigned int*)m)[i] != 0u;  // works for int32 1/0 and float32 1.0/0.0
}

__device__ __forceinline__ float dot4(float4 a, float4 b) {
    return a.x * b.x + a.y * b.y + a.z * b.z + a.w * b.w;
}

// ---------------- K_detect: classify mask element width --------------------
// For element value "true": uint8-bool buffer has byte[4i+1] nonzero w.p. 0.9;
// int32 (01 00 00 00) and float32 1.0f (00 00 80 3F) both have byte[4i+1]==0.
__global__ void k_detect(const unsigned char* __restrict__ mb) {
    if (threadIdx.x == 0 && blockIdx.x == 0) {
        int cnt = 0;
        for (int i = 0; i < 1024; i++) cnt += mb[i * 4 + 1] ? 1 : 0;
        g_mask_byte = (cnt > 64) ? 1 : 0;
    }
}

// ---------------- K0: per-batch masked-b count (denominator) ---------------
__global__ void k_denom(const void* __restrict__ mask_b) {
    int b = blockIdx.x, t = threadIdx.x;
    __shared__ int red[256];
    int c = 0;
    for (int q = t; q < NTOK; q += 256) c += mask_at(mask_b, b * NTOK + q) ? 1 : 0;
    red[t] = c;
    __syncthreads();
    for (int s = 128; s > 0; s >>= 1) {
        if (t < s) red[t] += red[t + s];
        __syncthreads();
    }
    if (t == 0) g_denom[b] = fmaxf((float)red[0], 1.0f);
}

// ---------------- K1: inverse norms of b tokens -----------------------------
__global__ void k_invb(const float* __restrict__ seq_b) {
    int tok  = blockIdx.x * 8 + (threadIdx.x >> 5);
    int lane = threadIdx.x & 31;
    const float4* p = (const float4*)(seq_b + (size_t)tok * H);
    float4 v0 = p[lane], v1 = p[lane + 32];
    float ss = dot4(v0, v0) + dot4(v1, v1);
#pragma unroll
    for (int off = 16; off > 0; off >>= 1)
        ss += __shfl_xor_sync(0xffffffffu, ss, off);
    if (lane == 0) g_invb[tok] = 1.0f / (sqrtf(ss) + EPSF);
}

// ---------------- K2a: partial masked sums of normalized b ------------------
__global__ void k_sb_part(const float* __restrict__ seq_b,
                          const void* __restrict__ mask_b) {
    int b = blockIdx.y, c = blockIdx.x, t = threadIdx.x;
    const float* Bb = seq_b + ((size_t)b * NTOK + c * 128) * H;
    const float* ib = g_invb + b * NTOK + c * 128;
    int mbase = b * NTOK + c * 128;
    float s = 0.f;
#pragma unroll 4
    for (int n = 0; n < 128; n++) {
        float sc = mask_at(mask_b, mbase + n) ? ib[n] : 0.0f;
        s += Bb[(size_t)n * H + t] * sc;
    }
    g_sb_part[c][b][t] = s;
}

// ---------------- K2b: reduce partial sums ----------------------------------
__global__ void k_sb_reduce() {
    int b = blockIdx.x, t = threadIdx.x;
    float s = 0.f;
#pragma unroll
    for (int c = 0; c < 8; c++) s += g_sb_part[c][b][t];
    g_sb[b * H + t] = s;
}

// ---------------- K3: a-token prep: word score, inv-norm, masked mean -------
__global__ void k_aprep(const float* __restrict__ seq_a,
                        const void* __restrict__ mask_a,
                        const float* __restrict__ w_word,
                        const float* __restrict__ b_word) {
    int tok  = blockIdx.x * 8 + (threadIdx.x >> 5);
    int lane = threadIdx.x & 31;
    int b    = tok >> 10;
    const float4* pa = (const float4*)(seq_a + (size_t)tok * H);
    const float4* pw = (const float4*)w_word;
    const float4* ps = (const float4*)(g_sb + b * H);
    float4 a0 = pa[lane], a1 = pa[lane + 32];
    float4 w0 = pw[lane], w1v = pw[lane + 32];
    float4 s0 = ps[lane], s1 = ps[lane + 32];
    float ss = dot4(a0, a0) + dot4(a1, a1);
    float dw = dot4(a0, w0) + dot4(a1, w1v);
    float ds = dot4(a0, s0) + dot4(a1, s1);
#pragma unroll
    for (int off = 16; off > 0; off >>= 1) {
        ss += __shfl_xor_sync(0xffffffffu, ss, off);
        dw += __shfl_xor_sync(0xffffffffu, dw, off);
        ds += __shfl_xor_sync(0xffffffffu, ds, off);
    }
    if (lane == 0) {
        float ma   = mask_at(mask_a, tok) ? 1.0f : 0.0f;
        float word = (dw + b_word[0]) * ma;
        float inva = 1.0f / (sqrtf(ss) + EPSF);
        g_word[tok] = word;
        g_inva[tok] = inva;
        g_mean[tok] = inva * ds / g_denom[b];
    }
}

// ---------------- K4: per-batch GEMM A(1024x256) x Bn^T with row-max --------
// BM=BN=128, BK=8, 256 threads, 8x8 per thread; block loops all 8 N-tiles.
__global__ __launch_bounds__(256, 2) void k_gemm_max(
    const float* __restrict__ seq_a, const float* __restrict__ seq_b) {
    int b   = blockIdx.y;
    int m0  = blockIdx.x * 128;
    int tid = threadIdx.x;
    int tx  = tid & 15, ty = tid >> 4;

    __shared__ float As[8][128];
    __shared__ float Bs[8][128];

    const float* Ab = seq_a + ((size_t)b * NTOK + m0) * H;
    const float* Bb = seq_b + (size_t)b * NTOK * H;

    int lrow = tid >> 1;
    int lcol = (tid & 1) * 4;

    float rowmax[8];
#pragma unroll
    for (int i = 0; i < 8; i++) rowmax[i] = -CUDART_INF_F;

    for (int nt = 0; nt < 8; nt++) {
        int n0 = nt * 128;
        float acc[8][8];
#pragma unroll
        for (int i = 0; i < 8; i++)
#pragma unroll
            for (int j = 0; j < 8; j++) acc[i][j] = 0.f;

        float ib = g_invb[b * NTOK + n0 + lrow];
        const float* Arow = Ab + (size_t)lrow * H + lcol;
        const float* Brow = Bb + (size_t)(n0 + lrow) * H + lcol;

        for (int kb = 0; kb < 32; kb++) {
            float4 av = *(const float4*)(Arow + kb * 8);
            float4 bv = *(const float4*)(Brow + kb * 8);
            As[lcol + 0][lrow] = av.x;
            As[lcol + 1][lrow] = av.y;
            As[lcol + 2][lrow] = av.z;
            As[lcol + 3][lrow] = av.w;
            Bs[lcol + 0][lrow] = bv.x * ib;
            Bs[lcol + 1][lrow] = bv.y * ib;
            Bs[lcol + 2][lrow] = bv.z * ib;
            Bs[lcol + 3][lrow] = bv.w * ib;
            __syncthreads();
#pragma unroll
            for (int k = 0; k < 8; k++) {
                float4 a0 = *(const float4*)&As[k][ty * 8];
                float4 a1 = *(const float4*)&As[k][ty * 8 + 4];
                float4 b0 = *(const float4*)&Bs[k][tx * 8];
                float4 b1 = *(const float4*)&Bs[k][tx * 8 + 4];
                float am[8] = {a0.x, a0.y, a0.z, a0.w, a1.x, a1.y, a1.z, a1.w};
                float bn[8] = {b0.x, b0.y, b0.z, b0.w, b1.x, b1.y, b1.z, b1.w};
#pragma unroll
                for (int i = 0; i < 8; i++)
#pragma unroll
                    for (int j = 0; j < 8; j++) acc[i][j] += am[i] * bn[j];
            }
            __syncthreads();
        }
#pragma unroll
        for (int i = 0; i < 8; i++) {
            float m = acc[i][0];
#pragma unroll
            for (int j = 1; j < 8; j++) m = fmaxf(m, acc[i][j]);
            rowmax[i] = fmaxf(rowmax[i], m);
        }
    }
    // reduce across the 16 threads (tx) sharing each row group
#pragma unroll
    for (int i = 0; i < 8; i++) {
        float v = rowmax[i];
        v = fmaxf(v, __shfl_xor_sync(0xffffffffu, v, 1));
        v = fmaxf(v, __shfl_xor_sync(0xffffffffu, v, 2));
        v = fmaxf(v, __shfl_xor_sync(0xffffffffu, v, 4));
        v = fmaxf(v, __shfl_xor_sync(0xffffffffu, v, 8));
        if (tx == 0) {
            int row = m0 + ty * 8 + i;
            g_max[b * NTOK + row] = g_inva[b * NTOK + row] * v;
        }
    }
}

// ---------------- K5: MLP logit + masked softmax + aggregation --------------
__global__ void k_final(const float* __restrict__ seq_a,
                        const void* __restrict__ mask_a,
                        const float* __restrict__ w1, const float* __restrict__ b1,
                        const float* __restrict__ w2, const float* __restrict__ b2,
                        float* __restrict__ out) {
    int br = blockIdx.x;  // b*16 + r
    int t  = threadIdx.x;
    __shared__ float wrd[64], mn[64], mx[64], feat[128], attn[64], red[256];

    if (t < 64) {
        int tok = br * RVL + t;
        wrd[t] = g_word[tok];
        mn[t]  = g_mean[tok];
        mx[t]  = g_max[tok];
    }
    __syncthreads();
    if (t < 128) {
        int l = t >> 1;
        feat[t] = ((t & 1) ? mx[l] : mn[l]) * wrd[l];
    }
    __syncthreads();

    float acc = b1[t];
#pragma unroll 4
    for (int f = 0; f < 128; f++) acc += feat[f] * w1[f * HID + t];
    red[t] = tanhf(acc) * w2[t];
    __syncthreads();
    for (int s = 128; s > 0; s >>= 1) {
        if (t < s) red[t] += red[t + s];
        __syncthreads();
    }
    if (t == 0) out[br] = red[0] + b2[0];

    if (t == 0) {
        float m = -CUDART_INF_F;
        for (int l = 0; l < 64; l++) {
            float s = mask_at(mask_a, br * RVL + l) ? wrd[l] : NEGV;
            attn[l] = s;
            if (s > m) m = s;
        }
        float ssum = 0.f;
        for (int l = 0; l < 64; l++) {
            float e = expf(attn[l] - m);
            attn[l] = e;
            ssum += e;
        }
        float inv = 1.0f / ssum;
        for (int l = 0; l < 64; l++) attn[l] *= inv;
    }
    __syncthreads();

    const float* A = seq_a + (size_t)br * RVL * H;
    float agg = 0.f;
#pragma unroll 8
    for (int l = 0; l < 64; l++) agg += attn[l] * A[(size_t)l * H + t];
    out[BZ * RVN + br * H + t] = agg;
}

// ---------------- launch -----------------------------------------------------
extern "C" void kernel_launch(void* const* d_in, const int* in_sizes, int n_in,
                              void* d_out, int out_size) {
    const float* seq_a = (const float*)d_in[0];
    const float* seq_b = (const float*)d_in[1];
    const void*  mask_a = d_in[2];
    const void*  mask_b = d_in[3];
    const float* w_word = (const float*)d_in[4];
    const float* b_word = (const float*)d_in[5];
    const float* w1 = (const float*)d_in[6];
    const float* b1 = (const float*)d_in[7];
    const float* w2 = (const float*)d_in[8];
    const float* b2 = (const float*)d_in[9];
    float* out = (float*)d_out;

    k_detect<<<1, 32>>>((const unsigned char*)mask_b);
    k_denom<<<BZ, 256>>>(mask_b);
    k_invb<<<BZ * NTOK / 8, 256>>>(seq_b);
    k_sb_part<<<dim3(8, BZ), 256>>>(seq_b, mask_b);
    k_sb_reduce<<<BZ, 256>>>();
    k_aprep<<<BZ * NTOK / 8, 256>>>(seq_a, mask_a, w_word, b_word);
    k_gemm_max<<<dim3(8, BZ), 256>>>(seq_a, seq_b);
    k_final<<<BZ * RVN, 256>>>(seq_a, mask_a, w1, b1, w2, b2, out);
}

// round 5
// speedup vs baseline: 2.0667x; 2.0667x over previous
#include <cuda_runtime.h>
#include <cuda_bf16.h>
#include <math_constants.h>
#include <cstdint>

#define BZ   32
#define RVN  16
#define RVL  64
#define H    256
#define NTOK 1024
#define HID  256
#define EPSF 1e-8f
#define NEGV -100000000.0f

// ---------------- scratch ----------------------------------------------------
__device__ __align__(16) float g_invb[BZ * NTOK];
__device__ __align__(16) float g_sb_part[32][BZ][H];
__device__ __align__(16) float g_sb[BZ * H];
__device__ __align__(16) float g_denom[BZ];
__device__ __align__(16) float g_word[BZ * NTOK];
__device__ __align__(16) float g_inva[BZ * NTOK];
__device__ __align__(16) float g_mean[BZ * NTOK];
__device__ __align__(16) float g_max[BZ * NTOK];
__device__ int g_mask_byte;
// bf16 hi/lo split operands (A raw, B pre-scaled by 1/||b||)
__device__ __align__(16) __nv_bfloat16 g_ah[BZ * NTOK * H];
__device__ __align__(16) __nv_bfloat16 g_al[BZ * NTOK * H];
__device__ __align__(16) __nv_bfloat16 g_bh[BZ * NTOK * H];
__device__ __align__(16) __nv_bfloat16 g_bl[BZ * NTOK * H];

__device__ __forceinline__ bool mask_at(const void* m, int i) {
    if (g_mask_byte) return ((const unsigned char*)m)[i] != 0;
    return ((const unsigned int*)m)[i] != 0u;
}
__device__ __forceinline__ float dot4(float4 a, float4 b) {
    return a.x * b.x + a.y * b.y + a.z * b.z + a.w * b.w;
}
__device__ __forceinline__ void cvt4(float4 v, float s,
                                     __nv_bfloat16* hp, __nv_bfloat16* lp) {
    float x0 = v.x * s, x1 = v.y * s, x2 = v.z * s, x3 = v.w * s;
    __nv_bfloat16 h0 = __float2bfloat16(x0), h1 = __float2bfloat16(x1);
    __nv_bfloat16 h2 = __float2bfloat16(x2), h3 = __float2bfloat16(x3);
    __nv_bfloat16 l0 = __float2bfloat16(x0 - __bfloat162float(h0));
    __nv_bfloat16 l1 = __float2bfloat16(x1 - __bfloat162float(h1));
    __nv_bfloat16 l2 = __float2bfloat16(x2 - __bfloat162float(h2));
    __nv_bfloat16 l3 = __float2bfloat16(x3 - __bfloat162float(h3));
    uint2 hu, lu;
    hu.x = (unsigned)__bfloat16_as_ushort(h0) | ((unsigned)__bfloat16_as_ushort(h1) << 16);
    hu.y = (unsigned)__bfloat16_as_ushort(h2) | ((unsigned)__bfloat16_as_ushort(h3) << 16);
    lu.x = (unsigned)__bfloat16_as_ushort(l0) | ((unsigned)__bfloat16_as_ushort(l1) << 16);
    lu.y = (unsigned)__bfloat16_as_ushort(l2) | ((unsigned)__bfloat16_as_ushort(l3) << 16);
    *(uint2*)hp = hu;
    *(uint2*)lp = lu;
}

// ---------------- mask width detect -----------------------------------------
__global__ void k_detect(const unsigned char* __restrict__ mb) {
    if (threadIdx.x == 0 && blockIdx.x == 0) {
        int cnt = 0;
        for (int i = 0; i < 1024; i++) cnt += mb[i * 4 + 1] ? 1 : 0;
        g_mask_byte = (cnt > 64) ? 1 : 0;
    }
}

// ---------------- denom -------------------------------------------------------
__global__ void k_denom(const void* __restrict__ mask_b) {
    int b = blockIdx.x, t = threadIdx.x;
    __shared__ int red[256];
    int c = 0;
    for (int q = t; q < NTOK; q += 256) c += mask_at(mask_b, b * NTOK + q) ? 1 : 0;
    red[t] = c;
    __syncthreads();
    for (int s = 128; s > 0; s >>= 1) {
        if (t < s) red[t] += red[t + s];
        __syncthreads();
    }
    if (t == 0) g_denom[b] = fmaxf((float)red[0], 1.0f);
}

// ---------------- b prep: invb + bf16 hi/lo of normalized b ------------------
__global__ void k_prep_b(const float* __restrict__ seq_b) {
    int tok  = blockIdx.x * 8 + (threadIdx.x >> 5);
    int lane = threadIdx.x & 31;
    const float4* p = (const float4*)(seq_b + (size_t)tok * H);
    float4 v0 = p[lane], v1 = p[lane + 32];
    float ss = dot4(v0, v0) + dot4(v1, v1);
#pragma unroll
    for (int off = 16; off > 0; off >>= 1)
        ss += __shfl_xor_sync(0xffffffffu, ss, off);
    float ib = 1.0f / (sqrtf(ss) + EPSF);
    if (lane == 0) g_invb[tok] = ib;
    size_t base = (size_t)tok * H;
    cvt4(v0, ib, g_bh + base + lane * 4, g_bl + base + lane * 4);
    cvt4(v1, ib, g_bh + base + 128 + lane * 4, g_bl + base + 128 + lane * 4);
}

// ---------------- masked sums of normalized b --------------------------------
__global__ void k_sb_part(const float* __restrict__ seq_b,
                          const void* __restrict__ mask_b) {
    int b = blockIdx.y, c = blockIdx.x, t = threadIdx.x;
    const float* Bb = seq_b + ((size_t)b * NTOK + c * 32) * H;
    const float* ib = g_invb + b * NTOK + c * 32;
    int mbase = b * NTOK + c * 32;
    float s = 0.f;
#pragma unroll 4
    for (int n = 0; n < 32; n++) {
        float sc = mask_at(mask_b, mbase + n) ? ib[n] : 0.0f;
        s += Bb[(size_t)n * H + t] * sc;
    }
    g_sb_part[c][b][t] = s;
}
__global__ void k_sb_reduce() {
    int b = blockIdx.x, t = threadIdx.x;
    float s = 0.f;
#pragma unroll
    for (int c = 0; c < 32; c++) s += g_sb_part[c][b][t];
    g_sb[b * H + t] = s;
}

// ---------------- a prep: word/inva/mean + bf16 hi/lo of a -------------------
__global__ void k_prep_a(const float* __restrict__ seq_a,
                         const void* __restrict__ mask_a,
                         const float* __restrict__ w_word,
                         const float* __restrict__ b_word) {
    int tok  = blockIdx.x * 8 + (threadIdx.x >> 5);
    int lane = threadIdx.x & 31;
    int b    = tok >> 10;
    const float4* pa = (const float4*)(seq_a + (size_t)tok * H);
    const float4* pw = (const float4*)w_word;
    const float4* ps = (const float4*)(g_sb + b * H);
    float4 a0 = pa[lane], a1 = pa[lane + 32];
    float4 w0 = pw[lane], w1v = pw[lane + 32];
    float4 s0 = ps[lane], s1 = ps[lane + 32];
    float ss = dot4(a0, a0) + dot4(a1, a1);
    float dw = dot4(a0, w0) + dot4(a1, w1v);
    float ds = dot4(a0, s0) + dot4(a1, s1);
#pragma unroll
    for (int off = 16; off > 0; off >>= 1) {
        ss += __shfl_xor_sync(0xffffffffu, ss, off);
        dw += __shfl_xor_sync(0xffffffffu, dw, off);
        ds += __shfl_xor_sync(0xffffffffu, ds, off);
    }
    float inva = 1.0f / (sqrtf(ss) + EPSF);
    if (lane == 0) {
        float ma   = mask_at(mask_a, tok) ? 1.0f : 0.0f;
        g_word[tok] = (dw + b_word[0]) * ma;
        g_inva[tok] = inva;
        g_mean[tok] = inva * ds / g_denom[b];
    }
    size_t base = (size_t)tok * H;
    cvt4(a0, 1.0f, g_ah + base + lane * 4, g_al + base + lane * 4);
    cvt4(a1, 1.0f, g_ah + base + 128 + lane * 4, g_al + base + 128 + lane * 4);
}

// ---------------- tensor-core GEMM with row-max epilogue ---------------------
// BM=128 (A fully K-resident in smem), 8 N-tiles of 128, K-chunk 64 per stage.
// 8 warps: wm=wid&3 (32 rows), wn=wid>>2 (64 cols). hi/lo 3-pass bf16 mma.
#define SMEM_U4 12288  // 4096 Ah + 4096 Al + 2*(1024 Bh + 1024 Bl)

__device__ __forceinline__ void ldsm4(uint32_t addr, uint32_t* r) {
    asm volatile("ldmatrix.sync.aligned.m8n8.x4.shared.b16 {%0,%1,%2,%3}, [%4];"
                 : "=r"(r[0]), "=r"(r[1]), "=r"(r[2]), "=r"(r[3]) : "r"(addr));
}
__device__ __forceinline__ void mma16816(float* c, const uint32_t* a,
                                         uint32_t b0, uint32_t b1) {
    asm volatile(
        "mma.sync.aligned.m16n8k16.row.col.f32.bf16.bf16.f32 "
        "{%0,%1,%2,%3}, {%4,%5,%6,%7}, {%8,%9}, {%0,%1,%2,%3};"
        : "+f"(c[0]), "+f"(c[1]), "+f"(c[2]), "+f"(c[3])
        : "r"(a[0]), "r"(a[1]), "r"(a[2]), "r"(a[3]), "r"(b0), "r"(b1));
}

__global__ __launch_bounds__(256, 1) void k_gemm_max() {
    extern __shared__ __align__(16) unsigned char smraw[];
    uint4* sm4 = (uint4*)smraw;
    uint32_t smb = (uint32_t)__cvta_generic_to_shared(smraw);

    const int b  = blockIdx.y;
    const int m0 = blockIdx.x * 128;
    const int tid = threadIdx.x, wid = tid >> 5, lane = tid & 31;
    const int wm = wid & 3, wn = wid >> 2;
    const int g = lane >> 3, ril = lane & 7;

    // --- load full-K A tiles (hi at 0, lo at 4096 uint4) ---
    const uint4* gah = (const uint4*)g_ah + (size_t)(b * NTOK + m0) * 32;
    const uint4* gal = (const uint4*)g_al + (size_t)(b * NTOK + m0) * 32;
#pragma unroll
    for (int i = 0; i < 16; i++) {
        int idx = tid + i * 256;
        int r = idx >> 5, c = idx & 31, cs = c ^ (r & 7);
        sm4[r * 32 + cs] = gah[r * 32 + c];
        sm4[4096 + r * 32 + cs] = gal[r * 32 + c];
    }

    // --- B prefetch registers ---
    uint4 pbh[4], pbl[4];
    const uint4* gbh = (const uint4*)g_bh + (size_t)b * NTOK * 32;
    const uint4* gbl = (const uint4*)g_bl + (size_t)b * NTOK * 32;

    auto loadB = [&](int nt2, int kc2) {
#pragma unroll
        for (int i = 0; i < 4; i++) {
            int idx = tid + i * 256;
            int r = idx >> 3, c = idx & 7;
            size_t gi = (size_t)(nt2 * 128 + r) * 32 + kc2 * 8 + c;
            pbh[i] = gbh[gi];
            pbl[i] = gbl[gi];
        }
    };
    loadB(0, 0);

    float pm[2][2];
    pm[0][0] = pm[0][1] = pm[1][0] = pm[1][1] = -CUDART_INF_F;
    float acc[2][8][4];

    for (int it = 0; it < 32; it++) {
        int kc = it & 3, buf = it & 1;
        // store prefetched B into smem (hi at 8192+buf*2048, lo +1024)
#pragma unroll
        for (int i = 0; i < 4; i++) {
            int idx = tid + i * 256;
            int r = idx >> 3, c = idx & 7, cs = c ^ (r & 7);
            sm4[8192 + buf * 2048 + r * 8 + cs] = pbh[i];
            sm4[8192 + buf * 2048 + 1024 + r * 8 + cs] = pbl[i];
        }
        __syncthreads();
        if (it < 31) {
            int nit = it + 1;
            loadB(nit >> 2, nit & 3);
        }
        if (kc == 0) {
#pragma unroll
            for (int mt = 0; mt < 2; mt++)
#pragma unroll
                for (int n = 0; n < 8; n++)
#pragma unroll
                    for (int q = 0; q < 4; q++) acc[mt][n][q] = 0.f;
        }
#pragma unroll
        for (int ks = 0; ks < 4; ks++) {
            uint32_t ah[2][4], al[2][4], bh[4][4], bl[4][4];
#pragma unroll
            for (int mt = 0; mt < 2; mt++) {
                int r = wm * 32 + mt * 16 + ((g & 1) << 3) + ril;
                int c = kc * 8 + ks * 2 + (g >> 1);
                int cs = c ^ (r & 7);
                ldsm4(smb + (uint32_t)(r * 32 + cs) * 16, ah[mt]);
                ldsm4(smb + (uint32_t)(4096 + r * 32 + cs) * 16, al[mt]);
            }
#pragma unroll
            for (int np = 0; np < 4; np++) {
                int r = wn * 64 + np * 16 + ((g & 1) << 3) + ril;
                int c = ks * 2 + (g >> 1);
                int cs = c ^ (r & 7);
                uint32_t base = 8192 + buf * 2048 + r * 8 + cs;
                ldsm4(smb + base * 16, bh[np]);
                ldsm4(smb + (base + 1024) * 16, bl[np]);
            }
            // ldmatrix x4 on B gives: [0]={n0-7,kLo} [1]={n8-15,kLo}
            //                         [2]={n0-7,kHi} [3]={n8-15,kHi}
            // mma wants b0=kLo, b1=kHi of ONE n-group: (frag[sub], frag[sub+2]).
#pragma unroll
            for (int mt = 0; mt < 2; mt++)
#pragma unroll
                for (int np = 0; np < 4; np++)
#pragma unroll
                    for (int sub = 0; sub < 2; sub++) {
                        float* c4 = acc[mt][np * 2 + sub];
                        uint32_t bx0 = bh[np][sub], bx1 = bh[np][sub + 2];
                        uint32_t by0 = bl[np][sub], by1 = bl[np][sub + 2];
                        mma16816(c4, ah[mt], bx0, bx1);
                        mma16816(c4, ah[mt], by0, by1);
                        mma16816(c4, al[mt], bx0, bx1);
                    }
        }
        if (kc == 3) {
#pragma unroll
            for (int mt = 0; mt < 2; mt++)
#pragma unroll
                for (int n = 0; n < 8; n++) {
                    pm[mt][0] = fmaxf(pm[mt][0], fmaxf(acc[mt][n][0], acc[mt][n][1]));
                    pm[mt][1] = fmaxf(pm[mt][1], fmaxf(acc[mt][n][2], acc[mt][n][3]));
                }
        }
    }

    // cross-lane and cross-warp max
    __syncthreads();
    float* mred = (float*)sm4;  // reuse A region: 128 rows x 2 wn
#pragma unroll
    for (int mt = 0; mt < 2; mt++)
#pragma unroll
        for (int hf = 0; hf < 2; hf++) {
            float v = pm[mt][hf];
            v = fmaxf(v, __shfl_xor_sync(0xffffffffu, v, 1));
            v = fmaxf(v, __shfl_xor_sync(0xffffffffu, v, 2));
            if ((lane & 3) == 0)
                mred[(wm * 32 + mt * 16 + hf * 8 + (lane >> 2)) * 2 + wn] = v;
        }
    __syncthreads();
    if (tid < 128) {
        float v = fmaxf(mred[tid * 2], mred[tid * 2 + 1]);
        int row = b * NTOK + m0 + tid;
        g_max[row] = v * g_inva[row];
    }
}

// ---------------- final: MLP logit + softmax + aggregation -------------------
__global__ void k_final(const float* __restrict__ seq_a,
                        const void* __restrict__ mask_a,
                        const float* __restrict__ w1, const float* __restrict__ b1,
                        const float* __restrict__ w2, const float* __restrict__ b2,
                        float* __restrict__ out) {
    int br = blockIdx.x;
    int t  = threadIdx.x;
    __shared__ float wrd[64], mn[64], mx[64], feat[128], attn[64], red[256];

    if (t < 64) {
        int tok = br * RVL + t;
        wrd[t] = g_word[tok];
        mn[t]  = g_mean[tok];
        mx[t]  = g_max[tok];
    }
    __syncthreads();
    if (t < 128) {
        int l = t >> 1;
        feat[t] = ((t & 1) ? mx[l] : mn[l]) * wrd[l];
    }
    __syncthreads();

    float acc = b1[t];
#pragma unroll 4
    for (int f = 0; f < 128; f++) acc += feat[f] * w1[f * HID + t];
    red[t] = tanhf(acc) * w2[t];
    __syncthreads();
    for (int s = 128; s > 0; s >>= 1) {
        if (t < s) red[t] += red[t + s];
        __syncthreads();
    }
    if (t == 0) out[br] = red[0] + b2[0];

    if (t == 0) {
        float m = -CUDART_INF_F;
        for (int l = 0; l < 64; l++) {
            float s = mask_at(mask_a, br * RVL + l) ? wrd[l] : NEGV;
            attn[l] = s;
            if (s > m) m = s;
        }
        float ssum = 0.f;
        for (int l = 0; l < 64; l++) {
            float e = expf(attn[l] - m);
            attn[l] = e;
            ssum += e;
        }
        float inv = 1.0f / ssum;
        for (int l = 0; l < 64; l++) attn[l] *= inv;
    }
    __syncthreads();

    const float* A = seq_a + (size_t)br * RVL * H;
    float agg = 0.f;
#pragma unroll 8
    for (int l = 0; l < 64; l++) agg += attn[l] * A[(size_t)l * H + t];
    out[BZ * RVN + br * H + t] = agg;
}

// ---------------- launch ------------------------------------------------------
extern "C" void kernel_launch(void* const* d_in, const int* in_sizes, int n_in,
                              void* d_out, int out_size) {
    const float* seq_a = (const float*)d_in[0];
    const float* seq_b = (const float*)d_in[1];
    const void*  mask_a = d_in[2];
    const void*  mask_b = d_in[3];
    const float* w_word = (const float*)d_in[4];
    const float* b_word = (const float*)d_in[5];
    const float* w1 = (const float*)d_in[6];
    const float* b1 = (const float*)d_in[7];
    const float* w2 = (const float*)d_in[8];
    const float* b2 = (const float*)d_in[9];
    float* out = (float*)d_out;

    cudaFuncSetAttribute(k_gemm_max, cudaFuncAttributeMaxDynamicSharedMemorySize,
                         SMEM_U4 * 16);

    k_detect<<<1, 32>>>((const unsigned char*)mask_b);
    k_denom<<<BZ, 256>>>(mask_b);
    k_prep_b<<<BZ * NTOK / 8, 256>>>(seq_b);
    k_sb_part<<<dim3(32, BZ), 256>>>(seq_b, mask_b);
    k_sb_reduce<<<BZ, 256>>>();
    k_prep_a<<<BZ * NTOK / 8, 256>>>(seq_a, mask_a, w_word, b_word);
    k_gemm_max<<<dim3(8, BZ), 256, SMEM_U4 * 16>>>();
    k_final<<<BZ * RVN, 256>>>(seq_a, mask_a, w1, b1, w2, b2, out);
}